// round 6
// baseline (speedup 1.0000x reference)
#include <cuda_runtime.h>
#include <mma.h>
#include <math.h>

using namespace nvcuda;

// Problem constants (fixed by the reference).
#define NTOK 8192     // B*S
#define HDIM 1024
#define FFDIM 4096
#define NEXP 8

// ---------------------------------------------------------------------------
// Scratch: __device__ globals (allocation inside kernel_launch is forbidden).
// ---------------------------------------------------------------------------
__device__ int   g_cnt[NEXP];
__device__ int   g_tok[NEXP][NTOK];     // expert -> token index list
__device__ int   g_slot[NEXP][NTOK];    // expert -> activation row (tok*2+j)
__device__ float g_cw[NEXP][NTOK];      // expert -> combine weight
__device__ float g_act[(size_t)2 * NTOK * FFDIM];   // 256 MB intermediate
__device__ float g_accum[(size_t)NTOK * HDIM];      // residual + expert outputs

// ---------------------------------------------------------------------------
// Kernel 0: init accumulator with residual, zero counters.
// ---------------------------------------------------------------------------
__global__ void init_kernel(const float* __restrict__ hidden) {
    if (blockIdx.x == 0 && threadIdx.x < NEXP) g_cnt[threadIdx.x] = 0;
    const size_t n4 = (size_t)NTOK * HDIM / 4;
    const float4* src = (const float4*)hidden;
    float4* dst = (float4*)g_accum;
    for (size_t i = (size_t)blockIdx.x * blockDim.x + threadIdx.x; i < n4;
         i += (size_t)gridDim.x * blockDim.x)
        dst[i] = src[i];
}

// ---------------------------------------------------------------------------
// Kernel 1: router. One CTA per token (256 threads = 8 warps = 8 experts).
// ---------------------------------------------------------------------------
__global__ void router_kernel(const float* __restrict__ x,
                              const float* __restrict__ rw,
                              const float* __restrict__ rb) {
    int tok = blockIdx.x;
    __shared__ float xs[HDIM];
    __shared__ float lg[NEXP];
    const float* xp = x + (size_t)tok * HDIM;
    for (int i = threadIdx.x; i < HDIM; i += blockDim.x) xs[i] = xp[i];
    __syncthreads();

    int w = threadIdx.x >> 5, lane = threadIdx.x & 31;
    {
        const float* wp = rw + (size_t)w * HDIM;
        float s = 0.f;
        for (int k = lane; k < HDIM; k += 32) s = fmaf(xs[k], wp[k], s);
        #pragma unroll
        for (int o = 16; o; o >>= 1) s += __shfl_xor_sync(0xffffffffu, s, o);
        if (lane == 0) lg[w] = s + rb[w];
    }
    __syncthreads();

    if (threadIdx.x == 0) {
        int i1 = 0; float v1 = lg[0];
        #pragma unroll
        for (int e = 1; e < NEXP; ++e) if (lg[e] > v1) { v1 = lg[e]; i1 = e; }
        int i2 = -1; float v2 = -3.0e38f;
        #pragma unroll
        for (int e = 0; e < NEXP; ++e)
            if (e != i1 && lg[e] > v2) { v2 = lg[e]; i2 = e; }
        // softmax over (v1 >= v2)
        float b = expf(v2 - v1);
        float inv = 1.f / (1.f + b);
        float cw1 = inv, cw2 = b * inv;

        int p1 = atomicAdd(&g_cnt[i1], 1);
        g_tok[i1][p1] = tok; g_slot[i1][p1] = tok * 2;     g_cw[i1][p1] = cw1;
        int p2 = atomicAdd(&g_cnt[i2], 1);
        g_tok[i2][p2] = tok; g_slot[i2][p2] = tok * 2 + 1; g_cw[i2][p2] = cw2;
    }
}

// ---------------------------------------------------------------------------
// GEMM tile machine: 128x128 block, BK=32, 8 warps (4x2), each warp 32x64
// via wmma m16n16k8 tf32 fragments. A rows gathered by index list.
// Smem: As/Bs 128x40 each; C staging 128x136 aliases them post-mainloop.
// ---------------------------------------------------------------------------
#define LDS_AB 40
#define LDS_C  136
#define SMEM_FLOATS (128 * LDS_C)   // 17408 floats = 69632 bytes (covers As+Bs)

__device__ __forceinline__ float gelu_exact(float v) {
    return 0.5f * v * (1.f + erff(v * 0.70710678118654752440f));
}

// Kernel 2: act[slot] = gelu(X[tok] @ W1[e]^T + b1[e])
__global__ void __launch_bounds__(256, 2)
gemm1_kernel(const float* __restrict__ X,
             const float* __restrict__ W1,
             const float* __restrict__ B1) {
    int e = blockIdx.z;
    int cnt = g_cnt[e];
    int m0 = blockIdx.y * 128;
    if (m0 >= cnt) return;
    int rows = min(cnt - m0, 128);
    int n0 = blockIdx.x * 128;

    extern __shared__ float smem[];
    float* As = smem;                  // 128 x 40
    float* Bs = smem + 128 * LDS_AB;   // 128 x 40
    float* Cs = smem;                  // 128 x 136 (after mainloop)

    __shared__ int toks[128];
    __shared__ int slots[128];
    for (int i = threadIdx.x; i < 128; i += 256) {
        toks[i]  = (i < rows) ? g_tok[e][m0 + i] : 0;
        slots[i] = (i < rows) ? g_slot[e][m0 + i] : 0;
    }
    __syncthreads();

    const float* wptr = W1 + (size_t)e * FFDIM * HDIM;

    wmma::fragment<wmma::accumulator, 16, 16, 8, float> acc[2][4];
    #pragma unroll
    for (int i = 0; i < 2; ++i)
        #pragma unroll
        for (int j = 0; j < 4; ++j) wmma::fill_fragment(acc[i][j], 0.f);

    int warp = threadIdx.x >> 5;
    int wm = warp >> 1;   // 0..3 (M direction)
    int wn = warp & 1;    // 0..1 (N direction)
    int t = threadIdx.x;

    for (int kt = 0; kt < HDIM / 32; ++kt) {
        int k0 = kt * 32;
        #pragma unroll
        for (int l = 0; l < 4; ++l) {            // A tile (gathered rows)
            int lin = t + 256 * l;
            int row = lin >> 3;
            int c4 = (lin & 7) * 4;
            float4 v = make_float4(0.f, 0.f, 0.f, 0.f);
            if (row < rows)
                v = *(const float4*)(X + (size_t)toks[row] * HDIM + k0 + c4);
            *(float4*)(As + row * LDS_AB + c4) = v;
        }
        #pragma unroll
        for (int l = 0; l < 4; ++l) {            // B tile: W1[e][n0+row][k]
            int lin = t + 256 * l;
            int row = lin >> 3;
            int c4 = (lin & 7) * 4;
            float4 v = *(const float4*)(wptr + (size_t)(n0 + row) * HDIM + k0 + c4);
            *(float4*)(Bs + row * LDS_AB + c4) = v;
        }
        __syncthreads();
        #pragma unroll
        for (int ks = 0; ks < 4; ++ks) {
            wmma::fragment<wmma::matrix_a, 16, 16, 8, wmma::precision::tf32, wmma::row_major> af[2];
            wmma::fragment<wmma::matrix_b, 16, 16, 8, wmma::precision::tf32, wmma::col_major> bf[4];
            #pragma unroll
            for (int i = 0; i < 2; ++i) {
                wmma::load_matrix_sync(af[i], As + (wm * 32 + i * 16) * LDS_AB + ks * 8, LDS_AB);
                #pragma unroll
                for (int q = 0; q < af[i].num_elements; ++q)
                    af[i].x[q] = wmma::__float_to_tf32(af[i].x[q]);
            }
            #pragma unroll
            for (int j = 0; j < 4; ++j) {
                wmma::load_matrix_sync(bf[j], Bs + (wn * 64 + j * 16) * LDS_AB + ks * 8, LDS_AB);
                #pragma unroll
                for (int q = 0; q < bf[j].num_elements; ++q)
                    bf[j].x[q] = wmma::__float_to_tf32(bf[j].x[q]);
            }
            #pragma unroll
            for (int i = 0; i < 2; ++i)
                #pragma unroll
                for (int j = 0; j < 4; ++j)
                    wmma::mma_sync(acc[i][j], af[i], bf[j], acc[i][j]);
        }
        __syncthreads();
    }

    #pragma unroll
    for (int i = 0; i < 2; ++i)
        #pragma unroll
        for (int j = 0; j < 4; ++j)
            wmma::store_matrix_sync(Cs + (wm * 32 + i * 16) * LDS_C + (wn * 64 + j * 16),
                                    acc[i][j], LDS_C, wmma::mem_row_major);
    __syncthreads();

    const float* b1p = B1 + (size_t)e * FFDIM + n0;
    for (int lin = t; lin < 128 * 128; lin += 256) {
        int row = lin >> 7, col = lin & 127;
        if (row < rows) {
            float v = Cs[row * LDS_C + col] + b1p[col];
            g_act[(size_t)slots[row] * FFDIM + n0 + col] = gelu_exact(v);
        }
    }
}

// Kernel 3: accum[tok] += cw * (act[slot] @ W2[e]^T + b2[e])
__global__ void __launch_bounds__(256, 2)
gemm2_kernel(const float* __restrict__ W2,
             const float* __restrict__ B2) {
    int e = blockIdx.z;
    int cnt = g_cnt[e];
    int m0 = blockIdx.y * 128;
    if (m0 >= cnt) return;
    int rows = min(cnt - m0, 128);
    int n0 = blockIdx.x * 128;

    extern __shared__ float smem[];
    float* As = smem;
    float* Bs = smem + 128 * LDS_AB;
    float* Cs = smem;

    __shared__ int toks[128];
    __shared__ int slots[128];
    __shared__ float cws[128];
    for (int i = threadIdx.x; i < 128; i += 256) {
        toks[i]  = (i < rows) ? g_tok[e][m0 + i] : 0;
        slots[i] = (i < rows) ? g_slot[e][m0 + i] : 0;
        cws[i]   = (i < rows) ? g_cw[e][m0 + i] : 0.f;
    }
    __syncthreads();

    const float* wptr = W2 + (size_t)e * HDIM * FFDIM;

    wmma::fragment<wmma::accumulator, 16, 16, 8, float> acc[2][4];
    #pragma unroll
    for (int i = 0; i < 2; ++i)
        #pragma unroll
        for (int j = 0; j < 4; ++j) wmma::fill_fragment(acc[i][j], 0.f);

    int warp = threadIdx.x >> 5;
    int wm = warp >> 1;
    int wn = warp & 1;
    int t = threadIdx.x;

    for (int kt = 0; kt < FFDIM / 32; ++kt) {
        int k0 = kt * 32;
        #pragma unroll
        for (int l = 0; l < 4; ++l) {            // A tile: act rows by slot
            int lin = t + 256 * l;
            int row = lin >> 3;
            int c4 = (lin & 7) * 4;
            float4 v = make_float4(0.f, 0.f, 0.f, 0.f);
            if (row < rows)
                v = *(const float4*)(g_act + (size_t)slots[row] * FFDIM + k0 + c4);
            *(float4*)(As + row * LDS_AB + c4) = v;
        }
        #pragma unroll
        for (int l = 0; l < 4; ++l) {            // B tile: W2[e][n0+row][k]
            int lin = t + 256 * l;
            int row = lin >> 3;
            int c4 = (lin & 7) * 4;
            float4 v = *(const float4*)(wptr + (size_t)(n0 + row) * FFDIM + k0 + c4);
            *(float4*)(Bs + row * LDS_AB + c4) = v;
        }
        __syncthreads();
        #pragma unroll
        for (int ks = 0; ks < 4; ++ks) {
            wmma::fragment<wmma::matrix_a, 16, 16, 8, wmma::precision::tf32, wmma::row_major> af[2];
            wmma::fragment<wmma::matrix_b, 16, 16, 8, wmma::precision::tf32, wmma::col_major> bf[4];
            #pragma unroll
            for (int i = 0; i < 2; ++i) {
                wmma::load_matrix_sync(af[i], As + (wm * 32 + i * 16) * LDS_AB + ks * 8, LDS_AB);
                #pragma unroll
                for (int q = 0; q < af[i].num_elements; ++q)
                    af[i].x[q] = wmma::__float_to_tf32(af[i].x[q]);
            }
            #pragma unroll
            for (int j = 0; j < 4; ++j) {
                wmma::load_matrix_sync(bf[j], Bs + (wn * 64 + j * 16) * LDS_AB + ks * 8, LDS_AB);
                #pragma unroll
                for (int q = 0; q < bf[j].num_elements; ++q)
                    bf[j].x[q] = wmma::__float_to_tf32(bf[j].x[q]);
            }
            #pragma unroll
            for (int i = 0; i < 2; ++i)
                #pragma unroll
                for (int j = 0; j < 4; ++j)
                    wmma::mma_sync(acc[i][j], af[i], bf[j], acc[i][j]);
        }
        __syncthreads();
    }

    #pragma unroll
    for (int i = 0; i < 2; ++i)
        #pragma unroll
        for (int j = 0; j < 4; ++j)
            wmma::store_matrix_sync(Cs + (wm * 32 + i * 16) * LDS_C + (wn * 64 + j * 16),
                                    acc[i][j], LDS_C, wmma::mem_row_major);
    __syncthreads();

    const float* b2p = B2 + (size_t)e * HDIM + n0;
    for (int lin = t; lin < 128 * 128; lin += 256) {
        int row = lin >> 7, col = lin & 127;
        if (row < rows) {
            float v = (Cs[row * LDS_C + col] + b2p[col]) * cws[row];
            atomicAdd(&g_accum[(size_t)toks[row] * HDIM + n0 + col], v);
        }
    }
}

// ---------------------------------------------------------------------------
// Kernel 4: LayerNorm over H per token (two-pass, matches reference).
// ---------------------------------------------------------------------------
__global__ void ln_kernel(const float* __restrict__ lw,
                          const float* __restrict__ lb,
                          float* __restrict__ out) {
    int tok = blockIdx.x;
    const float* xp = g_accum + (size_t)tok * HDIM;
    int t = threadIdx.x;
    float v[4];
    float s = 0.f;
    #pragma unroll
    for (int j = 0; j < 4; ++j) { v[j] = xp[t + 256 * j]; s += v[j]; }

    __shared__ float r1[8], r2[8];
    #pragma unroll
    for (int o = 16; o; o >>= 1) s += __shfl_xor_sync(0xffffffffu, s, o);
    if ((t & 31) == 0) r1[t >> 5] = s;
    __syncthreads();
    float mu = 0.f;
    #pragma unroll
    for (int i = 0; i < 8; ++i) mu += r1[i];
    mu *= (1.f / (float)HDIM);

    float s2 = 0.f;
    #pragma unroll
    for (int j = 0; j < 4; ++j) { float d = v[j] - mu; s2 += d * d; }
    #pragma unroll
    for (int o = 16; o; o >>= 1) s2 += __shfl_xor_sync(0xffffffffu, s2, o);
    if ((t & 31) == 0) r2[t >> 5] = s2;
    __syncthreads();
    float var = 0.f;
    #pragma unroll
    for (int i = 0; i < 8; ++i) var += r2[i];
    var *= (1.f / (float)HDIM);

    float rr = rsqrtf(var + 1e-12f);
    float* op = out + (size_t)tok * HDIM;
    #pragma unroll
    for (int j = 0; j < 4; ++j) {
        int c = t + 256 * j;
        op[c] = (v[j] - mu) * rr * lw[c] + lb[c];
    }
}

// ---------------------------------------------------------------------------
// kernel_launch
// ---------------------------------------------------------------------------
extern "C" void kernel_launch(void* const* d_in, const int* in_sizes, int n_in,
                              void* d_out, int out_size) {
    (void)in_sizes; (void)n_in; (void)out_size;
    const float* hidden = (const float*)d_in[0];
    const float* rw     = (const float*)d_in[1];
    const float* rb     = (const float*)d_in[2];
    const float* w1     = (const float*)d_in[3];
    const float* b1     = (const float*)d_in[4];
    const float* w2     = (const float*)d_in[5];
    const float* b2     = (const float*)d_in[6];
    const float* lw     = (const float*)d_in[7];
    const float* lb     = (const float*)d_in[8];
    float* out = (float*)d_out;

    const size_t smem_bytes = SMEM_FLOATS * sizeof(float);  // 69632
    cudaFuncSetAttribute(gemm1_kernel, cudaFuncAttributeMaxDynamicSharedMemorySize, (int)smem_bytes);
    cudaFuncSetAttribute(gemm2_kernel, cudaFuncAttributeMaxDynamicSharedMemorySize, (int)smem_bytes);

    init_kernel<<<2048, 256>>>(hidden);
    router_kernel<<<NTOK, 256>>>(hidden, rw, rb);
    gemm1_kernel<<<dim3(FFDIM / 128, NTOK / 128, NEXP), 256, smem_bytes>>>(hidden, w1, b1);
    gemm2_kernel<<<dim3(HDIM / 128, NTOK / 128, NEXP), 256, smem_bytes>>>(w2, b2);
    ln_kernel<<<NTOK, 256>>>(lw, lb, out);
}

// round 10
// speedup vs baseline: 1.2439x; 1.2439x over previous
#include <cuda_runtime.h>
#include <mma.h>
#include <math.h>

using namespace nvcuda;

// Problem constants (fixed by the reference).
#define NTOK 8192     // B*S
#define HDIM 1024
#define FFDIM 4096
#define NEXP 8

// ---------------------------------------------------------------------------
// Scratch: __device__ globals (allocation inside kernel_launch is forbidden).
// ---------------------------------------------------------------------------
__device__ int   g_cnt[NEXP];
__device__ int   g_tok[NEXP][NTOK];     // expert -> token index list
__device__ int   g_slot[NEXP][NTOK];    // expert -> activation row (tok*2+j)
__device__ float g_cw[NEXP][NTOK];      // expert -> combine weight
__device__ float g_act[(size_t)2 * NTOK * FFDIM]; // 256 MB intermediate
__device__ float g_y[(size_t)2 * NTOK * HDIM];    // per-slot expert outputs (64 MB)

// ---------------------------------------------------------------------------
// cp.async helper — plain immediate-size form only.
// Padded rows load from a valid dummy base; their results are never stored.
// ---------------------------------------------------------------------------
__device__ __forceinline__ void cp_async16(float* dst, const float* src) {
    unsigned int s = (unsigned int)__cvta_generic_to_shared(dst);
    asm volatile("cp.async.cg.shared.global [%0], [%1], 16;\n"
                 :: "r"(s), "l"(src));
}
#define CP_COMMIT() asm volatile("cp.async.commit_group;\n" ::)
#define CP_WAIT1()  asm volatile("cp.async.wait_group 1;\n" ::)

// ---------------------------------------------------------------------------
// Kernel 0: zero routing counters (graph replays must be deterministic).
// ---------------------------------------------------------------------------
__global__ void init_kernel() {
    if (threadIdx.x < NEXP) g_cnt[threadIdx.x] = 0;
}

// ---------------------------------------------------------------------------
// Kernel 1: router. One CTA per token (256 threads = 8 warps = 8 experts).
// ---------------------------------------------------------------------------
__global__ void router_kernel(const float* __restrict__ x,
                              const float* __restrict__ rw,
                              const float* __restrict__ rb) {
    int tok = blockIdx.x;
    __shared__ float xs[HDIM];
    __shared__ float lg[NEXP];
    const float* xp = x + (size_t)tok * HDIM;
    for (int i = threadIdx.x; i < HDIM; i += blockDim.x) xs[i] = xp[i];
    __syncthreads();

    int w = threadIdx.x >> 5, lane = threadIdx.x & 31;
    {
        const float* wp = rw + (size_t)w * HDIM;
        float s = 0.f;
        for (int k = lane; k < HDIM; k += 32) s = fmaf(xs[k], wp[k], s);
        #pragma unroll
        for (int o = 16; o; o >>= 1) s += __shfl_xor_sync(0xffffffffu, s, o);
        if (lane == 0) lg[w] = s + rb[w];
    }
    __syncthreads();

    if (threadIdx.x == 0) {
        int i1 = 0; float v1 = lg[0];
        #pragma unroll
        for (int e = 1; e < NEXP; ++e) if (lg[e] > v1) { v1 = lg[e]; i1 = e; }
        int i2 = -1; float v2 = -3.0e38f;
        #pragma unroll
        for (int e = 0; e < NEXP; ++e)
            if (e != i1 && lg[e] > v2) { v2 = lg[e]; i2 = e; }
        float b = expf(v2 - v1);
        float inv = 1.f / (1.f + b);
        float cw1 = inv, cw2 = b * inv;

        int p1 = atomicAdd(&g_cnt[i1], 1);
        g_tok[i1][p1] = tok; g_slot[i1][p1] = tok * 2;     g_cw[i1][p1] = cw1;
        int p2 = atomicAdd(&g_cnt[i2], 1);
        g_tok[i2][p2] = tok; g_slot[i2][p2] = tok * 2 + 1; g_cw[i2][p2] = cw2;
    }
}

// ---------------------------------------------------------------------------
// GEMM tile machine: 128x128 block, BK=32, 8 warps (4x2), warp 32x64 via
// wmma m16n16k8 tf32. cp.async double-buffered smem pipeline.
// Smem: 2 stages x (As 128x40 + Bs 128x40) = 20480 floats = 81920 bytes;
// C staging (128x136 = 17408 floats) aliases the stages post-mainloop.
// ---------------------------------------------------------------------------
#define LDS_AB 40
#define LDS_C  136
#define STAGE_FLOATS (2 * 128 * LDS_AB)          // As+Bs of one stage
#define SMEM_FLOATS  (2 * STAGE_FLOATS)          // 20480 floats = 81920 B

__device__ __forceinline__ float gelu_exact(float v) {
    return 0.5f * v * (1.f + erff(v * 0.70710678118654752440f));
}

using AccFrag = wmma::fragment<wmma::accumulator, 16, 16, 8, float>;

__device__ __forceinline__ void mma_tile(const float* As, const float* Bs,
                                         AccFrag acc[2][4], int wm, int wn) {
    #pragma unroll
    for (int ks = 0; ks < 4; ++ks) {
        wmma::fragment<wmma::matrix_a, 16, 16, 8, wmma::precision::tf32, wmma::row_major> af[2];
        wmma::fragment<wmma::matrix_b, 16, 16, 8, wmma::precision::tf32, wmma::col_major> bf[4];
        #pragma unroll
        for (int i = 0; i < 2; ++i) {
            wmma::load_matrix_sync(af[i], As + (wm * 32 + i * 16) * LDS_AB + ks * 8, LDS_AB);
            #pragma unroll
            for (int q = 0; q < af[i].num_elements; ++q)
                af[i].x[q] = wmma::__float_to_tf32(af[i].x[q]);
        }
        #pragma unroll
        for (int j = 0; j < 4; ++j) {
            wmma::load_matrix_sync(bf[j], Bs + (wn * 64 + j * 16) * LDS_AB + ks * 8, LDS_AB);
            #pragma unroll
            for (int q = 0; q < bf[j].num_elements; ++q)
                bf[j].x[q] = wmma::__float_to_tf32(bf[j].x[q]);
        }
        #pragma unroll
        for (int i = 0; i < 2; ++i)
            #pragma unroll
            for (int j = 0; j < 4; ++j)
                wmma::mma_sync(acc[i][j], af[i], bf[j], acc[i][j]);
    }
}

// Issue one stage of async loads: A rows gathered via rowoff[row] (padded
// rows point at offset 0 — valid memory, results discarded), B rows dense.
__device__ __forceinline__ void stage_load(float* As, float* Bs,
                                           const float* __restrict__ Abase,
                                           const int* rowoff,
                                           const float* __restrict__ wptr,
                                           int n0, int k0, int K, int t) {
    #pragma unroll
    for (int l = 0; l < 4; ++l) {
        int lin = t + 256 * l;
        int row = lin >> 3;
        int c4 = (lin & 7) * 4;
        cp_async16(As + row * LDS_AB + c4,
                   Abase + (size_t)rowoff[row] + k0 + c4);
    }
    #pragma unroll
    for (int l = 0; l < 4; ++l) {
        int lin = t + 256 * l;
        int row = lin >> 3;
        int c4 = (lin & 7) * 4;
        cp_async16(Bs + row * LDS_AB + c4,
                   wptr + (size_t)(n0 + row) * K + k0 + c4);
    }
}

// Kernel 2: act[slot] = gelu(X[tok] @ W1[e]^T + b1[e])
__global__ void __launch_bounds__(256, 2)
gemm1_kernel(const float* __restrict__ X,
             const float* __restrict__ W1,
             const float* __restrict__ B1) {
    int e = blockIdx.z;
    int cnt = g_cnt[e];
    int m0 = blockIdx.y * 128;
    if (m0 >= cnt) return;
    int rows = min(cnt - m0, 128);
    int n0 = blockIdx.x * 128;

    extern __shared__ float smem[];
    float* Cs = smem;

    __shared__ int aoff[128];     // per-row element offset into X (0 if padded)
    __shared__ int slots[128];
    for (int i = threadIdx.x; i < 128; i += 256) {
        int tk = (i < rows) ? g_tok[e][m0 + i] : 0;
        aoff[i]  = tk * HDIM;
        slots[i] = (i < rows) ? g_slot[e][m0 + i] : 0;
    }
    __syncthreads();

    const float* wptr = W1 + (size_t)e * FFDIM * HDIM;
    int t = threadIdx.x;
    int warp = t >> 5, wm = warp >> 1, wn = warp & 1;

    AccFrag acc[2][4];
    #pragma unroll
    for (int i = 0; i < 2; ++i)
        #pragma unroll
        for (int j = 0; j < 4; ++j) wmma::fill_fragment(acc[i][j], 0.f);

    const int NS = HDIM / 32;
    stage_load(smem, smem + 128 * LDS_AB, X, aoff, wptr, n0, 0, HDIM, t);
    CP_COMMIT();

    for (int kt = 0; kt < NS; ++kt) {
        int nb = (kt + 1) & 1;
        if (kt + 1 < NS)
            stage_load(smem + nb * STAGE_FLOATS, smem + nb * STAGE_FLOATS + 128 * LDS_AB,
                       X, aoff, wptr, n0, (kt + 1) * 32, HDIM, t);
        CP_COMMIT();
        CP_WAIT1();
        __syncthreads();
        int cb = kt & 1;
        mma_tile(smem + cb * STAGE_FLOATS, smem + cb * STAGE_FLOATS + 128 * LDS_AB,
                 acc, wm, wn);
        __syncthreads();
    }

    #pragma unroll
    for (int i = 0; i < 2; ++i)
        #pragma unroll
        for (int j = 0; j < 4; ++j)
            wmma::store_matrix_sync(Cs + (wm * 32 + i * 16) * LDS_C + (wn * 64 + j * 16),
                                    acc[i][j], LDS_C, wmma::mem_row_major);
    __syncthreads();

    const float* b1p = B1 + (size_t)e * FFDIM + n0;
    for (int lin = t; lin < 128 * 128; lin += 256) {
        int row = lin >> 7, col = lin & 127;
        if (row < rows) {
            float v = Cs[row * LDS_C + col] + b1p[col];
            g_act[(size_t)slots[row] * FFDIM + n0 + col] = gelu_exact(v);
        }
    }
}

// Kernel 3: g_y[slot] = cw * (act[slot] @ W2[e]^T + b2[e])
__global__ void __launch_bounds__(256, 2)
gemm2_kernel(const float* __restrict__ W2,
             const float* __restrict__ B2) {
    int e = blockIdx.z;
    int cnt = g_cnt[e];
    int m0 = blockIdx.y * 128;
    if (m0 >= cnt) return;
    int rows = min(cnt - m0, 128);
    int n0 = blockIdx.x * 128;

    extern __shared__ float smem[];
    float* Cs = smem;

    __shared__ int aoff[128];     // per-row element offset into g_act
    __shared__ int slots[128];
    __shared__ float cws[128];
    for (int i = threadIdx.x; i < 128; i += 256) {
        int sl = (i < rows) ? g_slot[e][m0 + i] : 0;
        aoff[i]  = sl * FFDIM;
        slots[i] = sl;
        cws[i]   = (i < rows) ? g_cw[e][m0 + i] : 0.f;
    }
    __syncthreads();

    const float* wptr = W2 + (size_t)e * HDIM * FFDIM;
    int t = threadIdx.x;
    int warp = t >> 5, wm = warp >> 1, wn = warp & 1;

    AccFrag acc[2][4];
    #pragma unroll
    for (int i = 0; i < 2; ++i)
        #pragma unroll
        for (int j = 0; j < 4; ++j) wmma::fill_fragment(acc[i][j], 0.f);

    const int NS = FFDIM / 32;
    stage_load(smem, smem + 128 * LDS_AB, g_act, aoff, wptr, n0, 0, FFDIM, t);
    CP_COMMIT();

    for (int kt = 0; kt < NS; ++kt) {
        int nb = (kt + 1) & 1;
        if (kt + 1 < NS)
            stage_load(smem + nb * STAGE_FLOATS, smem + nb * STAGE_FLOATS + 128 * LDS_AB,
                       g_act, aoff, wptr, n0, (kt + 1) * 32, FFDIM, t);
        CP_COMMIT();
        CP_WAIT1();
        __syncthreads();
        int cb = kt & 1;
        mma_tile(smem + cb * STAGE_FLOATS, smem + cb * STAGE_FLOATS + 128 * LDS_AB,
                 acc, wm, wn);
        __syncthreads();
    }

    #pragma unroll
    for (int i = 0; i < 2; ++i)
        #pragma unroll
        for (int j = 0; j < 4; ++j)
            wmma::store_matrix_sync(Cs + (wm * 32 + i * 16) * LDS_C + (wn * 64 + j * 16),
                                    acc[i][j], LDS_C, wmma::mem_row_major);
    __syncthreads();

    const float* b2p = B2 + (size_t)e * HDIM + n0;
    for (int lin = t; lin < 128 * 128; lin += 256) {
        int row = lin >> 7, col = lin & 127;
        if (row < rows) {
            float v = (Cs[row * LDS_C + col] + b2p[col]) * cws[row];
            g_y[(size_t)slots[row] * HDIM + n0 + col] = v;
        }
    }
}

// ---------------------------------------------------------------------------
// Kernel 4: out = LN(hidden + y[2t] + y[2t+1])  (two-pass, matches reference)
// ---------------------------------------------------------------------------
__global__ void ln_kernel(const float* __restrict__ hidden,
                          const float* __restrict__ lw,
                          const float* __restrict__ lb,
                          float* __restrict__ out) {
    int tok = blockIdx.x;
    const float* xp = hidden + (size_t)tok * HDIM;
    const float* y0 = g_y + (size_t)(2 * tok) * HDIM;
    const float* y1 = y0 + HDIM;
    int t = threadIdx.x;
    float v[4];
    float s = 0.f;
    #pragma unroll
    for (int j = 0; j < 4; ++j) {
        int c = t + 256 * j;
        v[j] = xp[c] + y0[c] + y1[c];
        s += v[j];
    }

    __shared__ float r1[8], r2[8];
    #pragma unroll
    for (int o = 16; o; o >>= 1) s += __shfl_xor_sync(0xffffffffu, s, o);
    if ((t & 31) == 0) r1[t >> 5] = s;
    __syncthreads();
    float mu = 0.f;
    #pragma unroll
    for (int i = 0; i < 8; ++i) mu += r1[i];
    mu *= (1.f / (float)HDIM);

    float s2 = 0.f;
    #pragma unroll
    for (int j = 0; j < 4; ++j) { float d = v[j] - mu; s2 += d * d; }
    #pragma unroll
    for (int o = 16; o; o >>= 1) s2 += __shfl_xor_sync(0xffffffffu, s2, o);
    if ((t & 31) == 0) r2[t >> 5] = s2;
    __syncthreads();
    float var = 0.f;
    #pragma unroll
    for (int i = 0; i < 8; ++i) var += r2[i];
    var *= (1.f / (float)HDIM);

    float rr = rsqrtf(var + 1e-12f);
    float* op = out + (size_t)tok * HDIM;
    #pragma unroll
    for (int j = 0; j < 4; ++j) {
        int c = t + 256 * j;
        op[c] = (v[j] - mu) * rr * lw[c] + lb[c];
    }
}

// ---------------------------------------------------------------------------
// kernel_launch
// ---------------------------------------------------------------------------
extern "C" void kernel_launch(void* const* d_in, const int* in_sizes, int n_in,
                              void* d_out, int out_size) {
    (void)in_sizes; (void)n_in; (void)out_size;
    const float* hidden = (const float*)d_in[0];
    const float* rw     = (const float*)d_in[1];
    const float* rb     = (const float*)d_in[2];
    const float* w1     = (const float*)d_in[3];
    const float* b1     = (const float*)d_in[4];
    const float* w2     = (const float*)d_in[5];
    const float* b2     = (const float*)d_in[6];
    const float* lw     = (const float*)d_in[7];
    const float* lb     = (const float*)d_in[8];
    float* out = (float*)d_out;

    const size_t smem_bytes = SMEM_FLOATS * sizeof(float);  // 81920
    cudaFuncSetAttribute(gemm1_kernel, cudaFuncAttributeMaxDynamicSharedMemorySize, (int)smem_bytes);
    cudaFuncSetAttribute(gemm2_kernel, cudaFuncAttributeMaxDynamicSharedMemorySize, (int)smem_bytes);

    init_kernel<<<1, 32>>>();
    router_kernel<<<NTOK, 256>>>(hidden, rw, rb);
    gemm1_kernel<<<dim3(FFDIM / 128, NTOK / 128, NEXP), 256, smem_bytes>>>(hidden, w1, b1);
    gemm2_kernel<<<dim3(HDIM / 128, NTOK / 128, NEXP), 256, smem_bytes>>>(w2, b2);
    ln_kernel<<<NTOK, 256>>>(hidden, lw, lb, out);
}